// round 15
// baseline (speedup 1.0000x reference)
#include <cuda_runtime.h>
#include <cuda_bf16.h>
#include <cstdint>

#define BATCH 2
#define NN 1024
#define ROWS (BATCH * NN)   // 2048
#define NBLOCKS 272
#define SCALE_Y 1.6983709f  // sqrt(2*log2e): t = <yh_i,yh_j> - R_i - R_j = -log2e*q

__device__ __nv_bfloat16 g_Yb[ROWS * 64];  // row-major, 128B rows
__device__ float g_R[ROWS];                // 0.5*||bf16(yh)||^2
__device__ int g_barrier_ctr;              // monotonic; replay-safe

__device__ __forceinline__ uint32_t smem_u32(const void* p) {
    uint32_t a;
    asm("{ .reg .u64 t; cvta.to.shared.u64 t, %1; cvt.u32.u64 %0, t; }" : "=r"(a) : "l"(p));
    return a;
}
__device__ __forceinline__ uint32_t swz128(uint32_t off) { return off ^ ((off >> 3) & 0x70); }

__device__ __forceinline__ void cpasync16(uint32_t dst, const void* src) {
    asm volatile("cp.async.cg.shared.global [%0], [%1], 16;" :: "r"(dst), "l"(src) : "memory");
}
__device__ __forceinline__ void cpasync4(uint32_t dst, const void* src) {
    asm volatile("cp.async.ca.shared.global [%0], [%1], 4;" :: "r"(dst), "l"(src) : "memory");
}

__device__ __forceinline__ void ldsm_x4(uint32_t r[4], uint32_t addr) {
    asm volatile("ldmatrix.sync.aligned.m8n8.x4.shared.b16 {%0,%1,%2,%3}, [%4];"
                 : "=r"(r[0]), "=r"(r[1]), "=r"(r[2]), "=r"(r[3]) : "r"(addr));
}
__device__ __forceinline__ void mma16816(float c[4], const uint32_t a[4],
                                         uint32_t b0, uint32_t b1) {
    asm volatile(
        "mma.sync.aligned.m16n8k16.row.col.f32.bf16.bf16.f32 "
        "{%0,%1,%2,%3}, {%4,%5,%6,%7}, {%8,%9}, {%0,%1,%2,%3};"
        : "+f"(c[0]), "+f"(c[1]), "+f"(c[2]), "+f"(c[3])
        : "r"(a[0]), "r"(a[1]), "r"(a[2]), "r"(a[3]), "r"(b0), "r"(b1));
}

// FFMA-only 2^t, deg-3.
__device__ __forceinline__ float exp2_poly(float tt) {
    const float MAGIC = 12582912.0f;     // 2^23 + 2^22
    const int   MAGIC_I = 0x4B400000;
    float sh = tt + MAGIC;
    float rn = sh - MAGIC;
    float f  = tt - rn;
    int   n  = __float_as_int(sh) - MAGIC_I;
    float p = 5.5504109e-2f;
    p = fmaf(p, f, 2.4022651e-1f);
    p = fmaf(p, f, 6.9314718e-1f);
    p = fmaf(p, f, 1.0f);
    float sc = __int_as_float((n + 127) << 23);
    return (n < -126) ? 0.0f : p * sc;
}

// ---------------------------------------------------------------------------
// Tile compute: 64(i) x 32(j), 4 warps, mma.sync bf16, poly-exp, direct STG
// + register mirror for strictly sub-diagonal tiles.
// ---------------------------------------------------------------------------
__device__ __forceinline__ void compute_tile(
    const __nv_bfloat16* As, const __nv_bfloat16* Bs,
    const float* Rish, const float* Rjsh,
    int ti, int tj, int b, float* __restrict__ out, int tid)
{
    const int wid = tid >> 5, lane = tid & 31;
    const uint32_t aBase = smem_u32(As), bBase = smem_u32(Bs);
    const int mrow0 = wid * 16;

    float acc[4][4];
    #pragma unroll
    for (int nb = 0; nb < 4; nb++)
        #pragma unroll
        for (int k = 0; k < 4; k++) acc[nb][k] = 0.f;

    #pragma unroll
    for (int ks = 0; ks < 4; ks++) {
        uint32_t a[4];
        const int arow = mrow0 + ((lane >> 3) & 1) * 8 + (lane & 7);
        const int kba  = ks * 32 + (lane >> 4) * 16;
        ldsm_x4(a, aBase + swz128(arow * 128 + kba));
        #pragma unroll
        for (int nb2 = 0; nb2 < 2; nb2++) {
            uint32_t bf[4];
            const int nrow = nb2 * 16 + ((lane >> 4) & 1) * 8 + (lane & 7);
            const int kbb  = ks * 32 + ((lane >> 3) & 1) * 16;
            ldsm_x4(bf, bBase + swz128(nrow * 128 + kbb));
            mma16816(acc[nb2 * 2],     a, bf[0], bf[1]);
            mma16816(acc[nb2 * 2 + 1], a, bf[2], bf[3]);
        }
    }

    const int rloc = lane >> 2;
    const float ri0 = Rish[mrow0 + rloc];
    const float ri1 = Rish[mrow0 + 8 + rloc];
    const bool diagTile = (tj == 2 * ti || tj == 2 * ti + 1);
    const bool mirror = (tj < 2 * ti);
    const size_t outBase = (size_t)b * NN * NN;
    const int gRow0 = ti * 64 + mrow0 + rloc;
    const int colOff = tj * 32;
    const size_t o0 = outBase + (size_t)gRow0 * NN + colOff;
    const size_t o1 = o0 + 8u * NN;

    #pragma unroll
    for (int nb = 0; nb < 4; nb++) {
        const int col0 = nb * 8 + (lane & 3) * 2;
        const float rj0 = Rjsh[col0], rj1 = Rjsh[col0 + 1];
        float e00 = exp2_poly((acc[nb][0] - ri0) - rj0);
        float e01 = exp2_poly((acc[nb][1] - ri0) - rj1);
        float e10 = exp2_poly((acc[nb][2] - ri1) - rj0);
        float e11 = exp2_poly((acc[nb][3] - ri1) - rj1);
        const int gcol0 = colOff + col0;
        if (diagTile) {
            if (gRow0 == gcol0)         e00 = 2.0f;
            if (gRow0 == gcol0 + 1)     e01 = 2.0f;
            if (gRow0 + 8 == gcol0)     e10 = 2.0f;
            if (gRow0 + 8 == gcol0 + 1) e11 = 2.0f;
        }
        *(float2*)&out[o0 + col0] = make_float2(e00, e01);
        *(float2*)&out[o1 + col0] = make_float2(e10, e11);
        if (mirror) {
            out[outBase + (size_t)(gcol0)     * NN + gRow0]     = e00;
            out[outBase + (size_t)(gcol0 + 1) * NN + gRow0]     = e01;
            out[outBase + (size_t)(gcol0)     * NN + gRow0 + 8] = e10;
            out[outBase + (size_t)(gcol0 + 1) * NN + gRow0 + 8] = e11;
        }
    }
}

// ---------------------------------------------------------------------------
// Fused single launch: phase 1 (blocks 0..255) computes Y + R; grid spin
// barrier (all 272 blocks co-resident: 4 warps, 25KB smem -> 8 blocks/SM
// capacity >> 272/148); phase 2 = R14's double-buffered tile kernel.
// ---------------------------------------------------------------------------
__global__ void __launch_bounds__(128) adj_all(const float* __restrict__ X,
                                               const float* __restrict__ W,
                                               float* __restrict__ out) {
    __shared__ __align__(1024) char arena[25600];
    const int tid = threadIdx.x;
    const int blk = blockIdx.x;

    // ---- Phase 1: Y = bf16(SCALE_Y * X @ W), R (blocks 0..255, 8 rows each)
    if (blk < 256) {
        float* Ws = (float*)arena;              // 16KB
        float* Xs = (float*)(arena + 16384);    // 2KB
        const int rowBase = blk * 8;

        #pragma unroll
        for (int i = tid; i < 1024; i += 128)
            ((float4*)Ws)[i] = ((const float4*)W)[i];
        ((float4*)Xs)[tid] = ((const float4*)(X + rowBase * 64))[tid];
        __syncthreads();

        const int warp = tid >> 5, lane = tid & 31;
        #pragma unroll
        for (int r = 0; r < 2; r++) {
            const int row = warp * 2 + r;
            float a0 = 0.f, a1 = 0.f;
            #pragma unroll
            for (int c0 = 0; c0 < 64; c0++) {
                const float xv = Xs[row * 64 + c0];
                a0 = fmaf(xv, Ws[c0 * 64 + lane],      a0);
                a1 = fmaf(xv, Ws[c0 * 64 + lane + 32], a1);
            }
            a0 *= SCALE_Y; a1 *= SCALE_Y;
            const __nv_bfloat16 b0 = __float2bfloat16(a0);
            const __nv_bfloat16 b1 = __float2bfloat16(a1);
            const float f0 = __bfloat162float(b0), f1 = __bfloat162float(b1);
            g_Yb[(rowBase + row) * 64 + lane]      = b0;
            g_Yb[(rowBase + row) * 64 + lane + 32] = b1;
            float s = f0 * f0 + f1 * f1;
            #pragma unroll
            for (int o = 16; o; o >>= 1) s += __shfl_xor_sync(0xffffffffu, s, o);
            if (lane == 0) g_R[rowBase + row] = 0.5f * s;
        }
        __syncthreads();   // arena reads done before phase 2 reuses it
    }

    // ---- Grid barrier (replay-safe monotonic ticket) ----
    if (tid == 0) {
        __threadfence();
        const int ticket = atomicAdd(&g_barrier_ctr, 1);
        const int target = (ticket / NBLOCKS + 1) * NBLOCKS;
        volatile int* vc = &g_barrier_ctr;
        while (*vc < target) { }
        __threadfence();
    }
    __syncthreads();

    // ---- Phase 2: triangular tile for both batches, double-buffered ----
    __nv_bfloat16* As0 = (__nv_bfloat16*)arena;            // 8KB
    __nv_bfloat16* As1 = (__nv_bfloat16*)(arena + 8192);   // 8KB
    __nv_bfloat16* Bs0 = (__nv_bfloat16*)(arena + 16384);  // 4KB
    __nv_bfloat16* Bs1 = (__nv_bfloat16*)(arena + 20480);  // 4KB
    float* Rbuf = (float*)(arena + 24576);                 // Ri0,Rj0,Ri1,Rj1
    float* Ri0 = Rbuf, *Rj0 = Rbuf + 64, *Ri1 = Rbuf + 96, *Rj1 = Rbuf + 160;

    const int t = blk;
    int ti = (int)((sqrtf(4.0f * (float)t + 1.0f) - 1.0f) * 0.5f);
    while ((ti + 1) * (ti + 2) <= t) ti++;
    while (ti * (ti + 1) > t) ti--;
    const int tj = t - ti * (ti + 1);

    #pragma unroll
    for (int s = 0; s < 2; s++) {
        const int gi = s * NN + ti * 64;
        const int gj = s * NN + tj * 32;
        const uint32_t uA = smem_u32(s ? As1 : As0), uB = smem_u32(s ? Bs1 : Bs0);
        #pragma unroll
        for (int it = 0; it < 4; it++) {
            const int idx = tid + it * 128;
            const int row = idx >> 3, ch = idx & 7;
            cpasync16(uA + swz128(row * 128 + ch * 16),
                      g_Yb + (size_t)(gi + row) * 64 + ch * 8);
        }
        #pragma unroll
        for (int it = 0; it < 2; it++) {
            const int idx = tid + it * 128;
            const int row = idx >> 3, ch = idx & 7;
            cpasync16(uB + swz128(row * 128 + ch * 16),
                      g_Yb + (size_t)(gj + row) * 64 + ch * 8);
        }
        float* RiS = s ? Ri1 : Ri0;
        float* RjS = s ? Rj1 : Rj0;
        if (tid < 64)       cpasync4(smem_u32(&RiS[tid]),      g_R + gi + tid);
        else if (tid < 96)  cpasync4(smem_u32(&RjS[tid - 64]), g_R + gj + (tid - 64));
        asm volatile("cp.async.commit_group;" ::: "memory");
    }

    asm volatile("cp.async.wait_group 1;" ::: "memory");
    __syncthreads();
    compute_tile(As0, Bs0, Ri0, Rj0, ti, tj, 0, out, tid);

    asm volatile("cp.async.wait_group 0;" ::: "memory");
    __syncthreads();
    compute_tile(As1, Bs1, Ri1, Rj1, ti, tj, 1, out, tid);
}

// ---------------------------------------------------------------------------
extern "C" void kernel_launch(void* const* d_in, const int* in_sizes, int n_in,
                              void* d_out, int out_size) {
    const float* X = (const float*)d_in[0];   // (2,1024,64)
    const float* W = (const float*)d_in[1];   // (64,64)
    float* out = (float*)d_out;               // (2,1024,1024)

    adj_all<<<NBLOCKS, 128>>>(X, W, out);
    (void)in_sizes; (void)n_in; (void)out_size;
}

// round 16
// speedup vs baseline: 1.0238x; 1.0238x over previous
#include <cuda_runtime.h>
#include <cuda_bf16.h>
#include <cstdint>

#define BATCH 2
#define NN 1024
#define ROWS (BATCH * NN)   // 2048
#define SCALE_Y 1.6983709f  // sqrt(2*log2e): t = <yh_i,yh_j> - R_i - R_j = -log2e*q

__device__ __nv_bfloat16 g_Yb[ROWS * 64];  // row-major, 128B rows
__device__ float g_R[ROWS];                // 0.5*||bf16(yh)||^2

__device__ __forceinline__ uint32_t smem_u32(const void* p) {
    uint32_t a;
    asm("{ .reg .u64 t; cvta.to.shared.u64 t, %1; cvt.u32.u64 %0, t; }" : "=r"(a) : "l"(p));
    return a;
}
__device__ __forceinline__ uint32_t swz128(uint32_t off) { return off ^ ((off >> 3) & 0x70); }

__device__ __forceinline__ void cpasync16(uint32_t dst, const void* src) {
    asm volatile("cp.async.cg.shared.global [%0], [%1], 16;" :: "r"(dst), "l"(src) : "memory");
}
__device__ __forceinline__ void cpasync4(uint32_t dst, const void* src) {
    asm volatile("cp.async.ca.shared.global [%0], [%1], 4;" :: "r"(dst), "l"(src) : "memory");
}

__device__ __forceinline__ void ldsm_x4(uint32_t r[4], uint32_t addr) {
    asm volatile("ldmatrix.sync.aligned.m8n8.x4.shared.b16 {%0,%1,%2,%3}, [%4];"
                 : "=r"(r[0]), "=r"(r[1]), "=r"(r[2]), "=r"(r[3]) : "r"(addr));
}
__device__ __forceinline__ void mma16816(float c[4], const uint32_t a[4],
                                         uint32_t b0, uint32_t b1) {
    asm volatile(
        "mma.sync.aligned.m16n8k16.row.col.f32.bf16.bf16.f32 "
        "{%0,%1,%2,%3}, {%4,%5,%6,%7}, {%8,%9}, {%0,%1,%2,%3};"
        : "+f"(c[0]), "+f"(c[1]), "+f"(c[2]), "+f"(c[3])
        : "r"(a[0]), "r"(a[1]), "r"(a[2]), "r"(a[3]), "r"(b0), "r"(b1));
}

// FFMA-only 2^t, deg-3.
__device__ __forceinline__ float exp2_poly(float tt) {
    const float MAGIC = 12582912.0f;     // 2^23 + 2^22
    const int   MAGIC_I = 0x4B400000;
    float sh = tt + MAGIC;
    float rn = sh - MAGIC;
    float f  = tt - rn;
    int   n  = __float_as_int(sh) - MAGIC_I;
    float p = 5.5504109e-2f;
    p = fmaf(p, f, 2.4022651e-1f);
    p = fmaf(p, f, 6.9314718e-1f);
    p = fmaf(p, f, 1.0f);
    float sc = __int_as_float((n + 127) << 23);
    return (n < -126) ? 0.0f : p * sc;
}

// ---------------------------------------------------------------------------
// Kernel A: yh = SCALE_Y * X @ W, bf16-rounded; R = 0.5*||bf16(yh)||^2.
// ---------------------------------------------------------------------------
__global__ void __launch_bounds__(128) y_kernel(const float* __restrict__ X,
                                                const float* __restrict__ W) {
    __shared__ float Ws[64 * 64];
    __shared__ float Xs[8 * 64];
    const int tid = threadIdx.x;
    const int rowBase = blockIdx.x * 8;

    #pragma unroll
    for (int i = tid; i < 1024; i += 128)
        ((float4*)Ws)[i] = ((const float4*)W)[i];
    ((float4*)Xs)[tid] = ((const float4*)(X + rowBase * 64))[tid];
    __syncthreads();

    const int warp = tid >> 5, lane = tid & 31;
    #pragma unroll
    for (int r = 0; r < 2; r++) {
        const int row = warp * 2 + r;
        float a0 = 0.f, a1 = 0.f;
        #pragma unroll
        for (int c0 = 0; c0 < 64; c0++) {
            const float xv = Xs[row * 64 + c0];
            a0 = fmaf(xv, Ws[c0 * 64 + lane],      a0);
            a1 = fmaf(xv, Ws[c0 * 64 + lane + 32], a1);
        }
        a0 *= SCALE_Y; a1 *= SCALE_Y;
        const __nv_bfloat16 b0 = __float2bfloat16(a0);
        const __nv_bfloat16 b1 = __float2bfloat16(a1);
        const float f0 = __bfloat162float(b0), f1 = __bfloat162float(b1);
        g_Yb[(rowBase + row) * 64 + lane]      = b0;
        g_Yb[(rowBase + row) * 64 + lane + 32] = b1;
        float s = f0 * f0 + f1 * f1;
        #pragma unroll
        for (int o = 16; o; o >>= 1) s += __shfl_xor_sync(0xffffffffu, s, o);
        if (lane == 0) g_R[rowBase + row] = 0.5f * s;
    }
}

// ---------------------------------------------------------------------------
// Kernel B: 272 blocks x 128 thr. Block t: triangular 64x32 tile t for BOTH
// batches, computed in ONE interleaved mainloop (two independent LDSM/MMA
// chains per warp -> 2x ILP at unchanged occupancy).
// ---------------------------------------------------------------------------
__global__ void __launch_bounds__(128) adj_kernel(float* __restrict__ out) {
    __shared__ __align__(1024) __nv_bfloat16 As[2][64 * 64];
    __shared__ __align__(1024) __nv_bfloat16 Bs[2][32 * 64];
    __shared__ float Ri[2][64], Rj[2][32];

    const int t = blockIdx.x;
    int ti = (int)((sqrtf(4.0f * (float)t + 1.0f) - 1.0f) * 0.5f);
    while ((ti + 1) * (ti + 2) <= t) ti++;
    while (ti * (ti + 1) > t) ti--;
    const int tj = t - ti * (ti + 1);

    const int tid = threadIdx.x;
    const int wid = tid >> 5, lane = tid & 31;

    // Prefetch both slots.
    #pragma unroll
    for (int s = 0; s < 2; s++) {
        const int gi = s * NN + ti * 64;
        const int gj = s * NN + tj * 32;
        const uint32_t uA = smem_u32(As[s]), uB = smem_u32(Bs[s]);
        #pragma unroll
        for (int it = 0; it < 4; it++) {
            const int idx = tid + it * 128;          // A: 512 x 16B
            const int row = idx >> 3, ch = idx & 7;
            cpasync16(uA + swz128(row * 128 + ch * 16),
                      g_Yb + (size_t)(gi + row) * 64 + ch * 8);
        }
        #pragma unroll
        for (int it = 0; it < 2; it++) {
            const int idx = tid + it * 128;          // B: 256 x 16B
            const int row = idx >> 3, ch = idx & 7;
            cpasync16(uB + swz128(row * 128 + ch * 16),
                      g_Yb + (size_t)(gj + row) * 64 + ch * 8);
        }
        if (tid < 64)       cpasync4(smem_u32(&Ri[s][tid]),      g_R + gi + tid);
        else if (tid < 96)  cpasync4(smem_u32(&Rj[s][tid - 64]), g_R + gj + (tid - 64));
    }
    asm volatile("cp.async.commit_group;" ::: "memory");
    asm volatile("cp.async.wait_group 0;" ::: "memory");
    __syncthreads();

    const uint32_t uA0 = smem_u32(As[0]), uA1 = smem_u32(As[1]);
    const uint32_t uB0 = smem_u32(Bs[0]), uB1 = smem_u32(Bs[1]);
    const int mrow0 = wid * 16;

    float acc[2][4][4];
    #pragma unroll
    for (int s = 0; s < 2; s++)
        #pragma unroll
        for (int nb = 0; nb < 4; nb++)
            #pragma unroll
            for (int k = 0; k < 4; k++) acc[s][nb][k] = 0.f;

    // Interleaved mainloop: two independent dependency chains per warp.
    #pragma unroll
    for (int ks = 0; ks < 4; ks++) {
        const int arow = mrow0 + ((lane >> 3) & 1) * 8 + (lane & 7);
        const int kba  = ks * 32 + (lane >> 4) * 16;
        const uint32_t aOff = swz128(arow * 128 + kba);
        uint32_t a0[4], a1[4];
        ldsm_x4(a0, uA0 + aOff);
        ldsm_x4(a1, uA1 + aOff);
        #pragma unroll
        for (int nb2 = 0; nb2 < 2; nb2++) {
            const int nrow = nb2 * 16 + ((lane >> 4) & 1) * 8 + (lane & 7);
            const int kbb  = ks * 32 + ((lane >> 3) & 1) * 16;
            const uint32_t bOff = swz128(nrow * 128 + kbb);
            uint32_t bf0[4], bf1[4];
            ldsm_x4(bf0, uB0 + bOff);
            ldsm_x4(bf1, uB1 + bOff);
            mma16816(acc[0][nb2 * 2],     a0, bf0[0], bf0[1]);
            mma16816(acc[1][nb2 * 2],     a1, bf1[0], bf1[1]);
            mma16816(acc[0][nb2 * 2 + 1], a0, bf0[2], bf0[3]);
            mma16816(acc[1][nb2 * 2 + 1], a1, bf1[2], bf1[3]);
        }
    }

    // Epilogue (both batches).
    const int rloc = lane >> 2;
    const bool diagTile = (tj == 2 * ti || tj == 2 * ti + 1);
    const bool mirror = (tj < 2 * ti);
    const int gRow0 = ti * 64 + mrow0 + rloc;
    const int colOff = tj * 32;

    #pragma unroll
    for (int s = 0; s < 2; s++) {
        const float ri0 = Ri[s][mrow0 + rloc];
        const float ri1 = Ri[s][mrow0 + 8 + rloc];
        const size_t outBase = (size_t)s * NN * NN;
        const size_t o0 = outBase + (size_t)gRow0 * NN + colOff;
        const size_t o1 = o0 + 8u * NN;
        #pragma unroll
        for (int nb = 0; nb < 4; nb++) {
            const int col0 = nb * 8 + (lane & 3) * 2;
            const float rj0 = Rj[s][col0], rj1 = Rj[s][col0 + 1];
            float e00 = exp2_poly((acc[s][nb][0] - ri0) - rj0);
            float e01 = exp2_poly((acc[s][nb][1] - ri0) - rj1);
            float e10 = exp2_poly((acc[s][nb][2] - ri1) - rj0);
            float e11 = exp2_poly((acc[s][nb][3] - ri1) - rj1);
            const int gcol0 = colOff + col0;
            if (diagTile) {
                if (gRow0 == gcol0)         e00 = 2.0f;
                if (gRow0 == gcol0 + 1)     e01 = 2.0f;
                if (gRow0 + 8 == gcol0)     e10 = 2.0f;
                if (gRow0 + 8 == gcol0 + 1) e11 = 2.0f;
            }
            *(float2*)&out[o0 + col0] = make_float2(e00, e01);
            *(float2*)&out[o1 + col0] = make_float2(e10, e11);
            if (mirror) {
                out[outBase + (size_t)(gcol0)     * NN + gRow0]     = e00;
                out[outBase + (size_t)(gcol0 + 1) * NN + gRow0]     = e01;
                out[outBase + (size_t)(gcol0)     * NN + gRow0 + 8] = e10;
                out[outBase + (size_t)(gcol0 + 1) * NN + gRow0 + 8] = e11;
            }
        }
    }
}

// ---------------------------------------------------------------------------
extern "C" void kernel_launch(void* const* d_in, const int* in_sizes, int n_in,
                              void* d_out, int out_size) {
    const float* X = (const float*)d_in[0];   // (2,1024,64)
    const float* W = (const float*)d_in[1];   // (64,64)
    float* out = (float*)d_out;               // (2,1024,1024)

    y_kernel<<<256, 128>>>(X, W);
    adj_kernel<<<272, 128>>>(out);
    (void)in_sizes; (void)n_in; (void)out_size;
}

// round 17
// speedup vs baseline: 1.0269x; 1.0030x over previous
#include <cuda_runtime.h>
#include <cuda_bf16.h>
#include <cstdint>

#define BATCH 2
#define NN 1024
#define ROWS (BATCH * NN)   // 2048
#define SCALE_Y 1.6983709f  // sqrt(2*log2e): t = <yh_i,yh_j> - R_i - R_j = -log2e*q

__device__ __nv_bfloat16 g_Yb[ROWS * 64];  // row-major, 128B rows
__device__ float g_R[ROWS];                // 0.5*||bf16(yh)||^2

__device__ __forceinline__ uint32_t smem_u32(const void* p) {
    uint32_t a;
    asm("{ .reg .u64 t; cvta.to.shared.u64 t, %1; cvt.u32.u64 %0, t; }" : "=r"(a) : "l"(p));
    return a;
}
__device__ __forceinline__ uint32_t swz128(uint32_t off) { return off ^ ((off >> 3) & 0x70); }

__device__ __forceinline__ void cpasync16(uint32_t dst, const void* src) {
    asm volatile("cp.async.cg.shared.global [%0], [%1], 16;" :: "r"(dst), "l"(src) : "memory");
}
__device__ __forceinline__ void cpasync4(uint32_t dst, const void* src) {
    asm volatile("cp.async.ca.shared.global [%0], [%1], 4;" :: "r"(dst), "l"(src) : "memory");
}

__device__ __forceinline__ void ldsm_x4(uint32_t r[4], uint32_t addr) {
    asm volatile("ldmatrix.sync.aligned.m8n8.x4.shared.b16 {%0,%1,%2,%3}, [%4];"
                 : "=r"(r[0]), "=r"(r[1]), "=r"(r[2]), "=r"(r[3]) : "r"(addr));
}
__device__ __forceinline__ void mma16816(float c[4], const uint32_t a[4],
                                         uint32_t b0, uint32_t b1) {
    asm volatile(
        "mma.sync.aligned.m16n8k16.row.col.f32.bf16.bf16.f32 "
        "{%0,%1,%2,%3}, {%4,%5,%6,%7}, {%8,%9}, {%0,%1,%2,%3};"
        : "+f"(c[0]), "+f"(c[1]), "+f"(c[2]), "+f"(c[3])
        : "r"(a[0]), "r"(a[1]), "r"(a[2]), "r"(a[3]), "r"(b0), "r"(b1));
}

// FFMA-only 2^t, deg-3.
__device__ __forceinline__ float exp2_poly(float tt) {
    const float MAGIC = 12582912.0f;     // 2^23 + 2^22
    const int   MAGIC_I = 0x4B400000;
    float sh = tt + MAGIC;
    float rn = sh - MAGIC;
    float f  = tt - rn;
    int   n  = __float_as_int(sh) - MAGIC_I;
    float p = 5.5504109e-2f;
    p = fmaf(p, f, 2.4022651e-1f);
    p = fmaf(p, f, 6.9314718e-1f);
    p = fmaf(p, f, 1.0f);
    float sc = __int_as_float((n + 127) << 23);
    return (n < -126) ? 0.0f : p * sc;
}

// ---------------------------------------------------------------------------
// Kernel A: yh = SCALE_Y * X @ W, bf16-rounded; R = 0.5*||bf16(yh)||^2.
// Triggers programmatic launch completion right after its last store.
// ---------------------------------------------------------------------------
__global__ void __launch_bounds__(128) y_kernel(const float* __restrict__ X,
                                                const float* __restrict__ W) {
    __shared__ float Ws[64 * 64];
    __shared__ float Xs[8 * 64];
    const int tid = threadIdx.x;
    const int rowBase = blockIdx.x * 8;

    #pragma unroll
    for (int i = tid; i < 1024; i += 128)
        ((float4*)Ws)[i] = ((const float4*)W)[i];
    ((float4*)Xs)[tid] = ((const float4*)(X + rowBase * 64))[tid];
    __syncthreads();

    const int warp = tid >> 5, lane = tid & 31;
    #pragma unroll
    for (int r = 0; r < 2; r++) {
        const int row = warp * 2 + r;
        float a0 = 0.f, a1 = 0.f;
        #pragma unroll
        for (int c0 = 0; c0 < 64; c0++) {
            const float xv = Xs[row * 64 + c0];
            a0 = fmaf(xv, Ws[c0 * 64 + lane],      a0);
            a1 = fmaf(xv, Ws[c0 * 64 + lane + 32], a1);
        }
        a0 *= SCALE_Y; a1 *= SCALE_Y;
        const __nv_bfloat16 b0 = __float2bfloat16(a0);
        const __nv_bfloat16 b1 = __float2bfloat16(a1);
        const float f0 = __bfloat162float(b0), f1 = __bfloat162float(b1);
        g_Yb[(rowBase + row) * 64 + lane]      = b0;
        g_Yb[(rowBase + row) * 64 + lane + 32] = b1;
        float s = f0 * f0 + f1 * f1;
        #pragma unroll
        for (int o = 16; o; o >>= 1) s += __shfl_xor_sync(0xffffffffu, s, o);
        if (lane == 0) g_R[rowBase + row] = 0.5f * s;
    }
    cudaTriggerProgrammaticLaunchCompletion();
}

// ---------------------------------------------------------------------------
// Kernel B (PDL secondary): pre-sync index math, cudaGridDependencySynchronize,
// then R16's interleaved dual-batch tile body.
// ---------------------------------------------------------------------------
__global__ void __launch_bounds__(128) adj_kernel(float* __restrict__ out) {
    __shared__ __align__(1024) __nv_bfloat16 As[2][64 * 64];
    __shared__ __align__(1024) __nv_bfloat16 Bs[2][32 * 64];
    __shared__ float Ri[2][64], Rj[2][32];

    const int t = blockIdx.x;
    int ti = (int)((sqrtf(4.0f * (float)t + 1.0f) - 1.0f) * 0.5f);
    while ((ti + 1) * (ti + 2) <= t) ti++;
    while (ti * (ti + 1) > t) ti--;
    const int tj = t - ti * (ti + 1);

    const int tid = threadIdx.x;
    const int wid = tid >> 5, lane = tid & 31;

    // Wait for y_kernel's grid (Y and R visible) before touching them.
    cudaGridDependencySynchronize();

    // Prefetch both slots.
    #pragma unroll
    for (int s = 0; s < 2; s++) {
        const int gi = s * NN + ti * 64;
        const int gj = s * NN + tj * 32;
        const uint32_t uA = smem_u32(As[s]), uB = smem_u32(Bs[s]);
        #pragma unroll
        for (int it = 0; it < 4; it++) {
            const int idx = tid + it * 128;          // A: 512 x 16B
            const int row = idx >> 3, ch = idx & 7;
            cpasync16(uA + swz128(row * 128 + ch * 16),
                      g_Yb + (size_t)(gi + row) * 64 + ch * 8);
        }
        #pragma unroll
        for (int it = 0; it < 2; it++) {
            const int idx = tid + it * 128;          // B: 256 x 16B
            const int row = idx >> 3, ch = idx & 7;
            cpasync16(uB + swz128(row * 128 + ch * 16),
                      g_Yb + (size_t)(gj + row) * 64 + ch * 8);
        }
        if (tid < 64)       cpasync4(smem_u32(&Ri[s][tid]),      g_R + gi + tid);
        else if (tid < 96)  cpasync4(smem_u32(&Rj[s][tid - 64]), g_R + gj + (tid - 64));
    }
    asm volatile("cp.async.commit_group;" ::: "memory");
    asm volatile("cp.async.wait_group 0;" ::: "memory");
    __syncthreads();

    const uint32_t uA0 = smem_u32(As[0]), uA1 = smem_u32(As[1]);
    const uint32_t uB0 = smem_u32(Bs[0]), uB1 = smem_u32(Bs[1]);
    const int mrow0 = wid * 16;

    float acc[2][4][4];
    #pragma unroll
    for (int s = 0; s < 2; s++)
        #pragma unroll
        for (int nb = 0; nb < 4; nb++)
            #pragma unroll
            for (int k = 0; k < 4; k++) acc[s][nb][k] = 0.f;

    // Interleaved mainloop: two independent dependency chains per warp.
    #pragma unroll
    for (int ks = 0; ks < 4; ks++) {
        const int arow = mrow0 + ((lane >> 3) & 1) * 8 + (lane & 7);
        const int kba  = ks * 32 + (lane >> 4) * 16;
        const uint32_t aOff = swz128(arow * 128 + kba);
        uint32_t a0[4], a1[4];
        ldsm_x4(a0, uA0 + aOff);
        ldsm_x4(a1, uA1 + aOff);
        #pragma unroll
        for (int nb2 = 0; nb2 < 2; nb2++) {
            const int nrow = nb2 * 16 + ((lane >> 4) & 1) * 8 + (lane & 7);
            const int kbb  = ks * 32 + ((lane >> 3) & 1) * 16;
            const uint32_t bOff = swz128(nrow * 128 + kbb);
            uint32_t bf0[4], bf1[4];
            ldsm_x4(bf0, uB0 + bOff);
            ldsm_x4(bf1, uB1 + bOff);
            mma16816(acc[0][nb2 * 2],     a0, bf0[0], bf0[1]);
            mma16816(acc[1][nb2 * 2],     a1, bf1[0], bf1[1]);
            mma16816(acc[0][nb2 * 2 + 1], a0, bf0[2], bf0[3]);
            mma16816(acc[1][nb2 * 2 + 1], a1, bf1[2], bf1[3]);
        }
    }

    // Epilogue (both batches).
    const int rloc = lane >> 2;
    const bool diagTile = (tj == 2 * ti || tj == 2 * ti + 1);
    const bool mirror = (tj < 2 * ti);
    const int gRow0 = ti * 64 + mrow0 + rloc;
    const int colOff = tj * 32;

    #pragma unroll
    for (int s = 0; s < 2; s++) {
        const float ri0 = Ri[s][mrow0 + rloc];
        const float ri1 = Ri[s][mrow0 + 8 + rloc];
        const size_t outBase = (size_t)s * NN * NN;
        const size_t o0 = outBase + (size_t)gRow0 * NN + colOff;
        const size_t o1 = o0 + 8u * NN;
        #pragma unroll
        for (int nb = 0; nb < 4; nb++) {
            const int col0 = nb * 8 + (lane & 3) * 2;
            const float rj0 = Rj[s][col0], rj1 = Rj[s][col0 + 1];
            float e00 = exp2_poly((acc[s][nb][0] - ri0) - rj0);
            float e01 = exp2_poly((acc[s][nb][1] - ri0) - rj1);
            float e10 = exp2_poly((acc[s][nb][2] - ri1) - rj0);
            float e11 = exp2_poly((acc[s][nb][3] - ri1) - rj1);
            const int gcol0 = colOff + col0;
            if (diagTile) {
                if (gRow0 == gcol0)         e00 = 2.0f;
                if (gRow0 == gcol0 + 1)     e01 = 2.0f;
                if (gRow0 + 8 == gcol0)     e10 = 2.0f;
                if (gRow0 + 8 == gcol0 + 1) e11 = 2.0f;
            }
            *(float2*)&out[o0 + col0] = make_float2(e00, e01);
            *(float2*)&out[o1 + col0] = make_float2(e10, e11);
            if (mirror) {
                out[outBase + (size_t)(gcol0)     * NN + gRow0]     = e00;
                out[outBase + (size_t)(gcol0 + 1) * NN + gRow0]     = e01;
                out[outBase + (size_t)(gcol0)     * NN + gRow0 + 8] = e10;
                out[outBase + (size_t)(gcol0 + 1) * NN + gRow0 + 8] = e11;
            }
        }
    }
}

// ---------------------------------------------------------------------------
extern "C" void kernel_launch(void* const* d_in, const int* in_sizes, int n_in,
                              void* d_out, int out_size) {
    const float* X = (const float*)d_in[0];   // (2,1024,64)
    const float* W = (const float*)d_in[1];   // (64,64)
    float* out = (float*)d_out;               // (2,1024,1024)

    y_kernel<<<256, 128>>>(X, W);

    // PDL: overlap adj launch/scheduling with y's tail.
    cudaLaunchConfig_t cfg = {};
    cfg.gridDim = dim3(272);
    cfg.blockDim = dim3(128);
    cfg.dynamicSmemBytes = 0;
    cudaLaunchAttribute attr[1];
    attr[0].id = cudaLaunchAttributeProgrammaticStreamSerialization;
    attr[0].val.programmaticStreamSerializationAllowed = 1;
    cfg.attrs = attr;
    cfg.numAttrs = 1;
    cudaLaunchKernelEx(&cfg, adj_kernel, (float*)out);

    (void)in_sizes; (void)n_in; (void)out_size;
}